// round 15
// baseline (speedup 1.0000x reference)
#include <cuda_runtime.h>
#include <cuda_fp16.h>
#include <math.h>
#include <stdint.h>

// Problem constants
#define S_ 8192
#define D_ 2048
#define H_ 64
#define E_ 64
#define L_ 64

#define NPART 256          // colsum partial blocks (32 rows each)
#define BM 32
#define BN 128
#define KC 32
#define NCH (D_ / KC)      // 64
#define NKK (D_ / 16)      // 128 k-steps of 16
#define RS 40              // smem row stride in fp16 (80 B, conflict-free ldsm)
#define NSTAGE 8

// dynamic smem stage layout (bytes): A only (fp16), 32 rows x RS
#define STAGE_BYTES 2560
#define SMEM_DYN (NSTAGE * STAGE_BYTES)   // 20480 (>= 16KB C overlay)

// Static device scratch
__device__ __align__(16) float g_vpart[NPART][D_];
__device__ __align__(16) float g_v[D_];
__device__ float g_gate[2];
__device__ int   g_idx[2];
__device__ __align__(16) uint16_t g_xhi[S_][D_];   // 32 MB (fp16 x)
// B (fp16 w) in MMA-fragment layout: [kk 128][warp_n 4][nn 2][lane 32] x uint4
__device__ uint4 g_wfrag[NKK * 4 * 2 * 32];        // 512 KB

__device__ __forceinline__ int wf_idx(int kk, int wn, int nn) {
    return (((kk << 2) + wn) * 2 + nn) << 5;
}

// ===========================================================================
// helpers
// ===========================================================================
__device__ __forceinline__ uint32_t smem_u32(const void* p) {
    uint32_t a;
    asm("{ .reg .u64 t; cvta.to.shared.u64 t, %1; cvt.u32.u64 %0, t; }"
        : "=r"(a) : "l"(p));
    return a;
}

__device__ __forceinline__ void cp16(uint32_t dst, const void* src) {
    asm volatile("cp.async.cg.shared.global [%0], [%1], 16;"
                 :: "r"(dst), "l"(src) : "memory");
}
#define CP_COMMIT() asm volatile("cp.async.commit_group;" ::: "memory")
#define CP_WAIT(n)  asm volatile("cp.async.wait_group %0;" :: "n"(n) : "memory")

__device__ __forceinline__ void ldsm4(uint32_t* r, uint32_t addr) {
    asm volatile("ldmatrix.sync.aligned.m8n8.x4.shared.b16 {%0,%1,%2,%3}, [%4];"
                 : "=r"(r[0]), "=r"(r[1]), "=r"(r[2]), "=r"(r[3]) : "r"(addr));
}

__device__ __forceinline__ void mma_f16(float* c, const uint32_t* a, const uint32_t* b) {
    asm volatile("mma.sync.aligned.m16n8k16.row.col.f32.f16.f16.f32 "
                 "{%0,%1,%2,%3}, {%4,%5,%6,%7}, {%8,%9}, {%0,%1,%2,%3};"
                 : "+f"(c[0]), "+f"(c[1]), "+f"(c[2]), "+f"(c[3])
                 : "r"(a[0]), "r"(a[1]), "r"(a[2]), "r"(a[3]), "r"(b[0]), "r"(b[1]));
}

__device__ __forceinline__ float gelu_exact(float v) {
    return 0.5f * v * (1.f + erff(v * 0.70710678118654752440f));
}

// ===========================================================================
// Kernel 1: fused weighted column-sum partials + fp16 quantization of x.
// 256 blocks x 32 rows.
// ===========================================================================
__global__ void __launch_bounds__(256) k_colsum_split(const float* __restrict__ x,
                                                      const float* __restrict__ wout) {
    __shared__ float ws[32];
    const int b = blockIdx.x, t = threadIdx.x;
    const int row0 = b * 32;
    if (t < 32) ws[t] = wout[row0 + t];
    __syncthreads();

    const int d0 = t * 8;
    float acc[8];
#pragma unroll
    for (int i = 0; i < 8; i++) acc[i] = 0.f;
    const float* xp = x + (size_t)row0 * D_ + d0;
#pragma unroll 4
    for (int r = 0; r < 32; r++) {
        const float w = ws[r];
        const float4 a = *(const float4*)(xp);
        const float4 c = *(const float4*)(xp + 4);
        acc[0] = fmaf(w, a.x, acc[0]); acc[1] = fmaf(w, a.y, acc[1]);
        acc[2] = fmaf(w, a.z, acc[2]); acc[3] = fmaf(w, a.w, acc[3]);
        acc[4] = fmaf(w, c.x, acc[4]); acc[5] = fmaf(w, c.y, acc[5]);
        acc[6] = fmaf(w, c.z, acc[6]); acc[7] = fmaf(w, c.w, acc[7]);
        uint4 hi;
        const __half2 h0 = __floats2half2_rn(a.x, a.y);
        const __half2 h1 = __floats2half2_rn(a.z, a.w);
        const __half2 h2 = __floats2half2_rn(c.x, c.y);
        const __half2 h3 = __floats2half2_rn(c.z, c.w);
        hi.x = *(const uint32_t*)&h0; hi.y = *(const uint32_t*)&h1;
        hi.z = *(const uint32_t*)&h2; hi.w = *(const uint32_t*)&h3;
        *(uint4*)&g_xhi[row0 + r][d0] = hi;
        xp += D_;
    }
#pragma unroll
    for (int i = 0; i < 8; i++) g_vpart[b][d0 + i] = acc[i];
}

// ===========================================================================
// Kernel 2a: v[d] = sum_b vpart[b][d]
// ===========================================================================
__global__ void __launch_bounds__(256) k_vreduce() {
    const int d = blockIdx.x * 256 + threadIdx.x;
    float s = 0.f;
#pragma unroll 8
    for (int b = 0; b < NPART; b++) s += g_vpart[b][d];
    g_v[d] = s;
}

// ===========================================================================
// Kernel 2b: fused gate: u = Wg_in@v; scores = Wg_lin@u; top-2; softmax.
// ===========================================================================
__global__ void __launch_bounds__(512) k_gate(const float* __restrict__ Wg_in,
                                              const float* __restrict__ Wg_lin) {
    __shared__ float v[D_];
    __shared__ float u[H_];
    __shared__ float sc[E_];
    const int t = threadIdx.x;
    for (int d = t; d < D_; d += 512) v[d] = g_v[d];
    __syncthreads();

    const int wid = t >> 5, lane = t & 31;
#pragma unroll
    for (int jj = 0; jj < 4; jj++) {
        const int j = wid * 4 + jj;
        const float* wr = Wg_in + (size_t)j * D_;
        float s = 0.f;
#pragma unroll
        for (int i = 0; i < 16; i++) {
            const float4 w = *(const float4*)(wr + i * 128 + lane * 4);
            const float4 vv = *(const float4*)(&v[i * 128 + lane * 4]);
            s += w.x * vv.x + w.y * vv.y + w.z * vv.z + w.w * vv.w;
        }
#pragma unroll
        for (int off = 16; off; off >>= 1) s += __shfl_down_sync(0xffffffffu, s, off);
        if (lane == 0) u[j] = s;
    }
    __syncthreads();

    if (t < E_) {
        float s = 0.f;
#pragma unroll
        for (int j = 0; j < H_; j++) s = fmaf(Wg_lin[t * H_ + j], u[j], s);
        sc[t] = s;
    }
    __syncthreads();

    if (t == 0) {
        int i0 = 0;
        for (int e = 1; e < E_; e++) if (sc[e] > sc[i0]) i0 = e;
        int i1 = (i0 == 0) ? 1 : 0;
        for (int e = 0; e < E_; e++) {
            if (e == i0 || e == i1) continue;
            if (sc[e] > sc[i1]) i1 = e;
        }
        const float e1 = expf(sc[i1] - sc[i0]);
        const float inv = 1.f / (1.f + e1);
        g_gate[0] = inv; g_gate[1] = e1 * inv;
        g_idx[0] = i0; g_idx[1] = i1;
    }
}

// ===========================================================================
// Kernel 2c: quantize the two selected experts' weights to fp16 DIRECTLY
// into MMA fragment layout (ldmatrix m8n8.x4 semantics: thread l holds
// rows l>>2, cols 2(l&3), 2(l&3)+1, +8 for the second reg). grid 128 x 256.
// ===========================================================================
__global__ void __launch_bounds__(256) k_wsplit(const float* __restrict__ We) {
    const int item = blockIdx.x * 256 + threadIdx.x;   // 0..32767
    const int lane = item & 31;
    const int nn   = (item >> 5) & 1;
    const int nt32 = (item >> 6) & 3;
    const int kk   = item >> 8;                         // 0..127

    uint4 hi;
#pragma unroll
    for (int j = 0; j < 2; j++) {
        const int n8t = nt32 * 4 + nn * 2 + j;          // 0..15
        const int e = g_idx[n8t >> 3];
        const int nrow = (n8t * 8 + (lane >> 2)) & 63;
        const float* src = We + ((size_t)e * L_ + nrow) * D_ + kk * 16 + 2 * (lane & 3);
        const __half2 h0 = __floats2half2_rn(src[0], src[1]);
        const __half2 h1 = __floats2half2_rn(src[8], src[9]);
        if (j == 0) { hi.x = *(const uint32_t*)&h0; hi.y = *(const uint32_t*)&h1; }
        else        { hi.z = *(const uint32_t*)&h0; hi.w = *(const uint32_t*)&h1; }
    }
    g_wfrag[wf_idx(kk, nt32, nn) + lane] = hi;
}

// ===========================================================================
// Kernel 3: HMMA expert GEMM, pure fp16. BM=32 -> grid 256 -> 2 CTAs/SM so
// co-resident CTAs hide each other's barrier/L2 stalls. A via cp.async
// 8-stage smem pipeline + LDSM; B fragments from global (fragment-ordered,
// L2-resident) in a chunk-granular register double buffer.
//   CTA: 32 rows x 128 cols; 8 warps 2x4; warp tile 16x32 via m16n8k16.
// ===========================================================================
__global__ void __launch_bounds__(256) k_expert(float* __restrict__ out) {
    extern __shared__ char dsm[];
    const uint32_t sbase = smem_u32(dsm);

    const int t = threadIdx.x;
    const int wid = t >> 5, lane = t & 31;
    const int row0 = blockIdx.x * BM;

    // ---- cp.async load mapping for A (16B segs; 32 rows x 4 segs = 128) ----
    const bool doA = t < 128;
    const int arow = t >> 2, aseg = t & 3;     // valid for t<128
    const uint16_t* gA = &g_xhi[row0 + (doA ? arow : 0)][aseg * 8];
    const uint32_t adst = (uint32_t)((doA ? arow : 0) * RS * 2 + aseg * 16);

    // ---- fragment mapping: warp grid 2(m) x 4(n), warp tile 16x32 ----
    const int warp_m = wid & 1, warp_n = wid >> 1;
    const int m_base = warp_m * 16, n_base = warp_n * 32;
    const int a_row = m_base + (lane & 15);
    const int a_k = (lane >> 4) << 3;
    const uint32_t fa = (uint32_t)(a_row * RS + a_k) * 2;

    float c[4][4];
#pragma unroll
    for (int nt = 0; nt < 4; nt++)
#pragma unroll
        for (int r = 0; r < 4; r++) c[nt][r] = 0.f;

    // ---- prologue: prefetch A stages 0..NSTAGE-2 ----
#pragma unroll
    for (int s = 0; s < NSTAGE - 1; s++) {
        if (doA) cp16(sbase + s * STAGE_BYTES + adst, gA + s * KC);
        CP_COMMIT();
    }

    // ---- B register double buffer: cur/nxt[ks][nn][4] ----
    uint32_t cur[2][2][4], nxt[2][2][4];
#pragma unroll
    for (int ks = 0; ks < 2; ks++)
#pragma unroll
        for (int nn = 0; nn < 2; nn++)
            *(uint4*)cur[ks][nn] = g_wfrag[wf_idx(ks, warp_n, nn) + lane];

#pragma unroll 1
    for (int ch = 0; ch < NCH; ++ch) {
        CP_WAIT(NSTAGE - 2);
        __syncthreads();

        const uint32_t tb = sbase + (ch & (NSTAGE - 1)) * STAGE_BYTES;

        // issue next A chunk into the stage just freed
        const int pf = ch + NSTAGE - 1;
        if (pf < NCH && doA)
            cp16(sbase + (pf & (NSTAGE - 1)) * STAGE_BYTES + adst, gA + pf * KC);
        CP_COMMIT();

        // load NEXT chunk's B fragments now (used after this chunk's MMAs)
        if (ch + 1 < NCH) {
#pragma unroll
            for (int ks = 0; ks < 2; ks++)
#pragma unroll
                for (int nn = 0; nn < 2; nn++)
                    *(uint4*)nxt[ks][nn] =
                        g_wfrag[wf_idx((ch + 1) * 2 + ks, warp_n, nn) + lane];
        }

#pragma unroll
        for (int ks = 0; ks < 2; ks++) {
            uint32_t a[4];
            ldsm4(a, tb + fa + ks * 32);
            // 4 independent MMAs (each accumulator touched once per k-step)
#pragma unroll
            for (int nt = 0; nt < 4; nt++)
                mma_f16(c[nt], a, &cur[ks][nt >> 1][(nt & 1) * 2]);
        }

        // rotate B buffers (register moves ride the alu pipe)
#pragma unroll
        for (int ks = 0; ks < 2; ks++)
#pragma unroll
            for (int nn = 0; nn < 2; nn++)
#pragma unroll
                for (int i = 0; i < 4; i++) cur[ks][nn][i] = nxt[ks][nn][i];
    }

    CP_WAIT(0);
    __syncthreads();

    // ---- stage C into smem (overlays stage space) ----
    float (*C)[BN] = (float (*)[BN])dsm;
#pragma unroll
    for (int nt = 0; nt < 4; nt++) {
        const int r0 = m_base + (lane >> 2);
        const int c0 = n_base + nt * 8 + 2 * (lane & 3);
        *(float2*)&C[r0][c0]     = make_float2(c[nt][0], c[nt][1]);
        *(float2*)&C[r0 + 8][c0] = make_float2(c[nt][2], c[nt][3]);
    }
    __syncthreads();

    // ---- epilogue: per-row L2 norm per expert half, GELU, gated combine ----
    const float g0 = g_gate[0], g1 = g_gate[1];
#pragma unroll
    for (int r = 0; r < 4; r++) {
        const int row = wid * 4 + r;
        const float z0a = C[row][lane];
        const float z0b = C[row][lane + 32];
        const float z1a = C[row][64 + lane];
        const float z1b = C[row][96 + lane];
        float ss0 = z0a * z0a + z0b * z0b;
        float ss1 = z1a * z1a + z1b * z1b;
#pragma unroll
        for (int off = 16; off; off >>= 1) {
            ss0 += __shfl_xor_sync(0xffffffffu, ss0, off);
            ss1 += __shfl_xor_sync(0xffffffffu, ss1, off);
        }
        const float inv0 = 1.f / fmaxf(sqrtf(ss0), 1e-12f);
        const float inv1 = 1.f / fmaxf(sqrtf(ss1), 1e-12f);
        float* orow = out + (size_t)(row0 + row) * L_;
        orow[lane]      = g0 * gelu_exact(z0a * inv0) + g1 * gelu_exact(z1a * inv1);
        orow[lane + 32] = g0 * gelu_exact(z0b * inv0) + g1 * gelu_exact(z1b * inv1);
    }
}

// ===========================================================================
extern "C" void kernel_launch(void* const* d_in, const int* in_sizes, int n_in,
                              void* d_out, int out_size) {
    const float* x      = (const float*)d_in[0];
    const float* Wg_in  = (const float*)d_in[1];
    const float* Wg_lin = (const float*)d_in[2];
    const float* Wg_out = (const float*)d_in[3];
    const float* We     = (const float*)d_in[4];
    float* out = (float*)d_out;

    cudaFuncSetAttribute(k_expert, cudaFuncAttributeMaxDynamicSharedMemorySize, SMEM_DYN);

    k_colsum_split<<<NPART, 256>>>(x, Wg_out);
    k_vreduce<<<8, 256>>>();
    k_gate<<<1, 512>>>(Wg_in, Wg_lin);
    k_wsplit<<<128, 256>>>(We);
    k_expert<<<S_ / BM, 256, SMEM_DYN>>>(out);
}